// round 14
// baseline (speedup 1.0000x reference)
#include <cuda_runtime.h>
#include <cuda_fp16.h>
#include <cstdint>

#define NV_    4096
#define B_     8
#define ND_    512
#define NODES_ 512

#define STEPF    ((0.99f - (-0.5f)) / 14.0f)
#define INV_STEP 9.3959731543624161f
#define HALF_INV_STEP 4.6979865771812080f
#define CORR_SCALE 2.44140625e-4f     // 2^-12

// Row-major fp16 tile images [4096 rows][128 k] = [4096][16] uint4 (1MB each).
// 2-term fp16 split: a = x0 + x1s*2^-12 (x1s stored pre-scaled by 2^12).
__device__ uint4 g_a0[4096 * 16];
__device__ uint4 g_a1[4096 * 16];     // scaled tail
__device__ uint4 g_b0[4096 * 16];
__device__ uint4 g_b1[4096 * 16];     // scaled tail
__device__ float g_part[32 * NV_];

// ---------------------------------------------------------------------------
// helpers
// ---------------------------------------------------------------------------
__device__ __forceinline__ uint32_t packhf(float a, float b) {
    __half2 t = __floats2half2_rn(a, b);
    return *reinterpret_cast<uint32_t*>(&t);
}
__device__ __forceinline__ uint32_t smem_u32(const void* p) {
    uint32_t a;
    asm("{ .reg .u64 t; cvta.to.shared.u64 t, %1; cvt.u32.u64 %0, t; }"
        : "=r"(a) : "l"(p));
    return a;
}
__device__ __forceinline__ void cp16(uint32_t dst, const void* src) {
    asm volatile("cp.async.cg.shared.global [%0], [%1], 16;"
                 :: "r"(dst), "l"(src) : "memory");
}
__device__ __forceinline__ void ldm_x4(uint32_t* r, uint32_t a) {
    asm volatile("ldmatrix.sync.aligned.m8n8.x4.shared.b16 {%0,%1,%2,%3}, [%4];"
                 : "=r"(r[0]), "=r"(r[1]), "=r"(r[2]), "=r"(r[3]) : "r"(a));
}
__device__ __forceinline__ void mma16816(float* c, const uint32_t* a,
                                         uint32_t b0, uint32_t b1) {
    asm volatile(
        "mma.sync.aligned.m16n8k16.row.col.f32.f16.f16.f32 "
        "{%0,%1,%2,%3}, {%4,%5,%6,%7}, {%8,%9}, {%0,%1,%2,%3};"
        : "+f"(c[0]), "+f"(c[1]), "+f"(c[2]), "+f"(c[3])
        : "r"(a[0]), "r"(a[1]), "r"(a[2]), "r"(a[3]), "r"(b0), "r"(b1));
}

// exact np.digitize vs f32 linspace boundaries b_k = -0.5f + k*STEPF
__device__ __forceinline__ float binval(float s, const float* __restrict__ binw) {
    float t = fmaf(s, INV_STEP, HALF_INV_STEP);
    int d = __float2int_rd(t) + 1;
    d = d < 0 ? 0 : (d > 15 ? 15 : d);
    float bd = -0.5f + (float)d * STEPF;
    if (d < 15 && s >= bd) d++;
    float bdm = -0.5f + (float)(d - 1) * STEPF;
    if (d > 0 && s < bdm) d--;
    return binw[d];
}

// 2-term fp16 split: a = h0 + h1*2^-12 (+ rho, |rho| <= 2^-24 |a|)
__device__ __forceinline__ void split2(float a, float& h0, float& h1s) {
    h0 = __half2float(__float2half_rn(a));
    float r = a - h0;                      // exact (Sterbenz)
    h1s = r * 4096.0f;                     // exact power-of-2 scale
}

// ---------------------------------------------------------------------------
// k0: gather emb rows + transpose VvT cols, 2-term fp16 split, write
// row-major [4096][128] fp16 images. Each of 65536 threads handles ONE A
// chunk AND ONE B chunk (MLP=2). Also zeroes the output buffer.
// ---------------------------------------------------------------------------
__global__ void __launch_bounds__(256)
k0_convert(const void* __restrict__ doc_raw,
           const float* __restrict__ emb,
           const float* __restrict__ vvt,
           float* __restrict__ out) {
    int t = blockIdx.x * blockDim.x + threadIdx.x;    // 0..65535
    if (t < B_ * NODES_) out[t] = 0.0f;               // zero out (poisoned)
    const long long* p64 = (const long long*)doc_raw;
    int is64 = 1;
    #pragma unroll
    for (int i = 0; i < 4; i++) {
        long long v = p64[i];
        if (v < 0 || v >= 50001LL) is64 = 0;
    }

    // --- B chunk: independent strided loads (issue first) ---
    int n = t & 4095, jb = t >> 12;
    float fb[8];
    #pragma unroll
    for (int i = 0; i < 8; i++)
        fb[i] = vvt[(size_t)(jb * 8 + i) * 4096 + n];

    // --- A chunk: dependent gather (overlaps with B loads) ---
    int ja = t & 15;
    int row = t >> 4;
    long long idx = is64 ? p64[row] : (long long)((const int*)doc_raw)[row];
    const float4* e4 = (const float4*)(emb + idx * 128);
    float4 va0 = e4[ja * 2], va1 = e4[ja * 2 + 1];
    float fa[8] = {va0.x, va0.y, va0.z, va0.w, va1.x, va1.y, va1.z, va1.w};

    // --- convert & store both ---
    uint32_t a0[4], a1[4], b0[4], b1[4];
    #pragma unroll
    for (int i = 0; i < 4; i++) {
        float x0, x1, y0, y1;
        split2(fa[2 * i], x0, x1);
        split2(fa[2 * i + 1], y0, y1);
        a0[i] = packhf(x0, y0);
        a1[i] = packhf(x1, y1);
        split2(fb[2 * i], x0, x1);
        split2(fb[2 * i + 1], y0, y1);
        b0[i] = packhf(x0, y0);
        b1[i] = packhf(x1, y1);
    }
    g_a0[t] = make_uint4(a0[0], a0[1], a0[2], a0[3]);
    g_a1[t] = make_uint4(a1[0], a1[1], a1[2], a1[3]);
    g_b0[n * 16 + jb] = make_uint4(b0[0], b0[1], b0[2], b0[3]);
    g_b1[n * 16 + jb] = make_uint4(b1[0], b1[1], b1[2], b1[3]);
}

// ---------------------------------------------------------------------------
// k1: HMMA fp16 2-term-split GEMM tile (128m x 64n, K=128; x0y0 -> main,
// x1sy0 + x0y1s -> corr, all f32 accum) + fused digitize epilogue.
// 2 CTAs/SM; 256 threads = 8 warps (4m x 2n), warp tile 32m x 32n.
// cp.async groups staggered: g1 = A0+B0, g2 = A1, g3 = B1.
// ---------------------------------------------------------------------------
#define ROWB  272            // bytes per smem row (136 halves)
#define BUFA  (128 * ROWB)   // 34816 B
#define BUFBN (64 * ROWB)    // 17408 B
#define SMEM_DYN (2 * BUFA + 2 * BUFBN)   // 104448 B

__device__ __forceinline__ void run_pass(uint32_t uA, uint32_t uB,
                                         float (*acc)[4][4],
                                         uint32_t a_off, uint32_t b_off) {
    #pragma unroll
    for (int ks = 0; ks < 8; ks++) {
        uint32_t kb = ks * 32;               // 16 halves per k-step
        uint32_t a0[4], a1[4];
        ldm_x4(a0, uA + a_off + kb);
        ldm_x4(a1, uA + a_off + 16 * ROWB + kb);
        #pragma unroll
        for (int nf16 = 0; nf16 < 2; nf16++) {
            uint32_t b[4];
            ldm_x4(b, uB + b_off + nf16 * 16 * ROWB + kb);
            mma16816(acc[0][nf16 * 2],     a0, b[0], b[1]);
            mma16816(acc[0][nf16 * 2 + 1], a0, b[2], b[3]);
            mma16816(acc[1][nf16 * 2],     a1, b[0], b[1]);
            mma16816(acc[1][nf16 * 2 + 1], a1, b[2], b[3]);
        }
    }
}

__global__ void __launch_bounds__(256, 2)
k1_mma(const float* __restrict__ attn,
       const float* __restrict__ diff,
       const float* __restrict__ start) {
    extern __shared__ char dynsm[];
    __shared__ float s_binw[16];
    __shared__ float s_attn[128];
    __shared__ float s_red2[4 * 64];

    const int tid  = threadIdx.x;
    const int lane = tid & 31;
    const int wid  = tid >> 5;
    const int warp_m = wid & 3, warp_n = wid >> 2;
    const int nb = blockIdx.x, mb = blockIdx.y;

    const uint32_t uS  = smem_u32(dynsm);
    const uint32_t uA0 = uS;
    const uint32_t uA1 = uS + BUFA;
    const uint32_t uB0 = uS + 2 * BUFA;
    const uint32_t uB1 = uS + 2 * BUFA + BUFBN;

    if (tid < 128) s_attn[tid] = attn[mb * 128 + tid];
    if (tid == 0) {
        float s0 = start[0], acc = 0.0f;
        for (int i = 0; i < 16; i++) {
            float dv = diff[i];
            acc += (dv > 0.0f) ? dv : 0.0f;
            s_binw[i] = s0 + acc;
        }
    }

    // async loads: g1 = A0,B0 ; g2 = A1 ; g3 = B1
    {
        const uint4* ga0 = g_a0 + mb * 2048;
        const uint4* gb0 = g_b0 + nb * 1024;
        #pragma unroll
        for (int c = tid; c < 2048; c += 256) {
            uint32_t d = (uint32_t)(c >> 4) * ROWB + (uint32_t)(c & 15) * 16;
            cp16(uA0 + d, ga0 + c);
        }
        #pragma unroll
        for (int c = tid; c < 1024; c += 256) {
            uint32_t d = (uint32_t)(c >> 4) * ROWB + (uint32_t)(c & 15) * 16;
            cp16(uB0 + d, gb0 + c);
        }
        asm volatile("cp.async.commit_group;" ::: "memory");
        const uint4* ga1 = g_a1 + mb * 2048;
        #pragma unroll
        for (int c = tid; c < 2048; c += 256) {
            uint32_t d = (uint32_t)(c >> 4) * ROWB + (uint32_t)(c & 15) * 16;
            cp16(uA1 + d, ga1 + c);
        }
        asm volatile("cp.async.commit_group;" ::: "memory");
        const uint4* gb1 = g_b1 + nb * 1024;
        #pragma unroll
        for (int c = tid; c < 1024; c += 256) {
            uint32_t d = (uint32_t)(c >> 4) * ROWB + (uint32_t)(c & 15) * 16;
            cp16(uB1 + d, gb1 + c);
        }
        asm volatile("cp.async.commit_group;" ::: "memory");
    }

    // per-thread ldmatrix lane offsets
    const uint32_t a_off = (uint32_t)(warp_m * 32 + (lane & 15)) * ROWB +
                           (uint32_t)(lane >> 4) * 16;
    const int bn = (lane & 7) + ((lane >> 4) << 3);
    const uint32_t b_off = (uint32_t)(warp_n * 32 + bn) * ROWB +
                           (uint32_t)((lane >> 3) & 1) * 16;

    float accm[2][4][4];     // main: x0*y0
    float accc[2][4][4];     // corr: 2^12*(x1*y0 + x0*y1)
    #pragma unroll
    for (int i = 0; i < 2; i++)
        #pragma unroll
        for (int j = 0; j < 4; j++)
            #pragma unroll
            for (int q = 0; q < 4; q++) { accm[i][j][q] = 0.0f; accc[i][j][q] = 0.0f; }

    asm volatile("cp.async.wait_group 2;" ::: "memory");   // g1 done
    __syncthreads();
    run_pass(uA0, uB0, accm, a_off, b_off);      // x0*y0
    asm volatile("cp.async.wait_group 1;" ::: "memory");   // g2 (A1) done
    __syncthreads();
    run_pass(uA1, uB0, accc, a_off, b_off);      // x1s*y0
    asm volatile("cp.async.wait_group 0;" ::: "memory");   // g3 (B1) done
    __syncthreads();
    run_pass(uA0, uB1, accc, a_off, b_off);      // x0*y1s

    __syncthreads();   // done reading tile buffers; reuse as red[128][68]

    // ---- epilogue: combine, digitize + attn weight -> red, column reduce ----
    float* red = (float*)dynsm;                  // stride 68 (even -> float2 ok)
    {
        const int r0b = warp_m * 32 + (lane >> 2);
        const int colb = warp_n * 32 + (lane & 3) * 2;
        #pragma unroll
        for (int mf = 0; mf < 2; mf++) {
            int ra = r0b + mf * 16;
            float aa = s_attn[ra], ab = s_attn[ra + 8];
            #pragma unroll
            for (int nf = 0; nf < 4; nf++) {
                int cc = colb + nf * 8;
                float* fm = accm[mf][nf];
                float* fc = accc[mf][nf];
                float s0v = fmaf(fc[0], CORR_SCALE, fm[0]);
                float s1v = fmaf(fc[1], CORR_SCALE, fm[1]);
                float s2v = fmaf(fc[2], CORR_SCALE, fm[2]);
                float s3v = fmaf(fc[3], CORR_SCALE, fm[3]);
                // paired stores: (cc, cc+1) adjacent -> single STS.64
                *(float2*)&red[ra * 68 + cc] =
                    make_float2(aa * binval(s0v, s_binw), aa * binval(s1v, s_binw));
                *(float2*)&red[(ra + 8) * 68 + cc] =
                    make_float2(ab * binval(s2v, s_binw), ab * binval(s3v, s_binw));
            }
        }
    }
    __syncthreads();
    {
        int col = tid & 63, seg = tid >> 6;      // 4 segs of 32 rows
        float s0 = 0.f, s1 = 0.f;
        #pragma unroll 8
        for (int r = seg * 32; r < seg * 32 + 32; r += 2) {
            s0 += red[r * 68 + col];
            s1 += red[(r + 1) * 68 + col];
        }
        s_red2[seg * 64 + col] = s0 + s1;
    }
    __syncthreads();
    if (tid < 64)
        g_part[mb * NV_ + nb * 64 + tid] =
            (s_red2[tid] + s_red2[64 + tid]) +
            (s_red2[128 + tid] + s_red2[192 + tid]);
}

// ---------------------------------------------------------------------------
// k2: blocked GEMM out[b,j] += sum_{v in split} a[b,v]*phi[j,v].
// grid (4 v-splits, 32 j-tiles of 16); atomicAdd into out (zeroed by k0).
// ---------------------------------------------------------------------------
__global__ void __launch_bounds__(256)
k2_gemm2(const float* __restrict__ phi, float* __restrict__ out) {
    __shared__ float asum[8 * 1024];
    const int vs = blockIdx.x, jt = blockIdx.y;
    const int tid = threadIdx.x;
    const int vbase = vs * 1024;

    for (int i = tid; i < 8192; i += 256) {
        int b = i >> 10, v = i & 1023;
        int gv = vbase + v;
        asum[i] = (g_part[(4 * b + 0) * NV_ + gv] + g_part[(4 * b + 1) * NV_ + gv]) +
                  (g_part[(4 * b + 2) * NV_ + gv] + g_part[(4 * b + 3) * NV_ + gv]);
    }
    __syncthreads();

    const int wid = tid >> 5, lane = tid & 31;
    const float4* asum4 = (const float4*)asum;
    #pragma unroll 4
    for (int c = 0; c < 16; c++) {
        int cid = wid * 16 + c;
        int jl = cid >> 3, b = cid & 7;
        int j = jt * 16 + jl;
        const float4* p4 = (const float4*)(phi + (size_t)j * NV_ + vbase);
        float acc = 0.f;
        #pragma unroll
        for (int it = 0; it < 8; it++) {
            float4 a4 = asum4[b * 256 + it * 32 + lane];
            float4 pp = p4[it * 32 + lane];
            acc = fmaf(a4.x, pp.x, acc);
            acc = fmaf(a4.y, pp.y, acc);
            acc = fmaf(a4.z, pp.z, acc);
            acc = fmaf(a4.w, pp.w, acc);
        }
        #pragma unroll
        for (int o = 16; o > 0; o >>= 1)
            acc += __shfl_xor_sync(0xffffffffu, acc, o);
        if (lane == 0) atomicAdd(&out[b * NODES_ + j], acc);
    }
}

// ---------------------------------------------------------------------------
extern "C" void kernel_launch(void* const* d_in, const int* in_sizes, int n_in,
                              void* d_out, int out_size) {
    const void*  doc   = d_in[0];
    const float* attn  = (const float*)d_in[1];
    const float* emb   = (const float*)d_in[2];
    const float* vvt   = (const float*)d_in[3];
    const float* phi   = (const float*)d_in[4];
    const float* diff  = (const float*)d_in[5];
    const float* start = (const float*)d_in[6];
    float* out = (float*)d_out;

    static int smem_set = 0;
    if (!smem_set) {
        cudaFuncSetAttribute(k1_mma, cudaFuncAttributeMaxDynamicSharedMemorySize,
                             SMEM_DYN);
        smem_set = 1;
    }

    k0_convert<<<256, 256>>>(doc, emb, vvt, out);
    dim3 g1(NV_ / 64, (B_ * ND_) / 128);           // 64 x 32
    k1_mma<<<g1, 256, SMEM_DYN>>>(attn, diff, start);
    dim3 g2(4, 32);
    k2_gemm2<<<g2, 256>>>(phi, out);
}

// round 15
// speedup vs baseline: 1.0320x; 1.0320x over previous
#include <cuda_runtime.h>
#include <cuda_fp16.h>
#include <cstdint>

#define NV_    4096
#define B_     8
#define ND_    512
#define NODES_ 512

#define STEPF    ((0.99f - (-0.5f)) / 14.0f)
#define INV_STEP 9.3959731543624161f
#define HALF_INV_STEP 4.6979865771812080f
#define CORR_SCALE 2.44140625e-4f     // 2^-12

// Row-major fp16 tile images [4096 rows][128 k] = [4096][16] uint4 (1MB each).
// 2-term fp16 split: a = x0 + x1s*2^-12 (x1s stored pre-scaled by 2^12).
__device__ uint4 g_a0[4096 * 16];
__device__ uint4 g_a1[4096 * 16];     // scaled tail
__device__ uint4 g_b0[4096 * 16];
__device__ uint4 g_b1[4096 * 16];     // scaled tail
__device__ float g_part[32 * NV_];

// ---------------------------------------------------------------------------
// helpers
// ---------------------------------------------------------------------------
__device__ __forceinline__ uint32_t packhf(float a, float b) {
    __half2 t = __floats2half2_rn(a, b);
    return *reinterpret_cast<uint32_t*>(&t);
}
__device__ __forceinline__ uint32_t smem_u32(const void* p) {
    uint32_t a;
    asm("{ .reg .u64 t; cvta.to.shared.u64 t, %1; cvt.u32.u64 %0, t; }"
        : "=r"(a) : "l"(p));
    return a;
}
__device__ __forceinline__ void cp16(uint32_t dst, const void* src) {
    asm volatile("cp.async.cg.shared.global [%0], [%1], 16;"
                 :: "r"(dst), "l"(src) : "memory");
}
__device__ __forceinline__ void ldm_x4(uint32_t* r, uint32_t a) {
    asm volatile("ldmatrix.sync.aligned.m8n8.x4.shared.b16 {%0,%1,%2,%3}, [%4];"
                 : "=r"(r[0]), "=r"(r[1]), "=r"(r[2]), "=r"(r[3]) : "r"(a));
}
__device__ __forceinline__ void mma16816(float* c, const uint32_t* a,
                                         uint32_t b0, uint32_t b1) {
    asm volatile(
        "mma.sync.aligned.m16n8k16.row.col.f32.f16.f16.f32 "
        "{%0,%1,%2,%3}, {%4,%5,%6,%7}, {%8,%9}, {%0,%1,%2,%3};"
        : "+f"(c[0]), "+f"(c[1]), "+f"(c[2]), "+f"(c[3])
        : "r"(a[0]), "r"(a[1]), "r"(a[2]), "r"(a[3]), "r"(b0), "r"(b1));
}

// exact np.digitize vs f32 linspace boundaries b_k = -0.5f + k*STEPF
__device__ __forceinline__ float binval(float s, const float* __restrict__ binw) {
    float t = fmaf(s, INV_STEP, HALF_INV_STEP);
    int d = __float2int_rd(t) + 1;
    d = d < 0 ? 0 : (d > 15 ? 15 : d);
    float bd = -0.5f + (float)d * STEPF;
    if (d < 15 && s >= bd) d++;
    float bdm = -0.5f + (float)(d - 1) * STEPF;
    if (d > 0 && s < bdm) d--;
    return binw[d];
}

// 2-term fp16 split: a = h0 + h1*2^-12 (+ rho, |rho| <= 2^-24 |a|)
__device__ __forceinline__ void split2(float a, float& h0, float& h1s) {
    h0 = __half2float(__float2half_rn(a));
    float r = a - h0;                      // exact (Sterbenz)
    h1s = r * 4096.0f;                     // exact power-of-2 scale
}

// ---------------------------------------------------------------------------
// k0: gather emb rows / transpose VvT cols, 2-term fp16 split, write
// row-major [4096][128] fp16 images. Thread-per-(row, 8-float-chunk):
// 131072 threads across 512 blocks (full-chip, latency-hiding).
// Also zeroes the output buffer (k2 accumulates into it atomically).
// ---------------------------------------------------------------------------
__global__ void __launch_bounds__(256)
k0_convert(const void* __restrict__ doc_raw,
           const float* __restrict__ emb,
           const float* __restrict__ vvt,
           float* __restrict__ out) {
    int t = blockIdx.x * blockDim.x + threadIdx.x;    // 0..131071
    if (t < B_ * NODES_) out[t] = 0.0f;               // zero out (poisoned)
    const long long* p64 = (const long long*)doc_raw;
    int is64 = 1;
    #pragma unroll
    for (int i = 0; i < 4; i++) {
        long long v = p64[i];
        if (v < 0 || v >= 50001LL) is64 = 0;
    }
    if (t < 65536) {                                  // A: (row, j)
        int row = t >> 4, j = t & 15;
        long long idx = is64 ? p64[row] : (long long)((const int*)doc_raw)[row];
        const float4* e4 = (const float4*)(emb + idx * 128);
        float4 v0 = e4[j * 2], v1 = e4[j * 2 + 1];
        float f[8] = {v0.x, v0.y, v0.z, v0.w, v1.x, v1.y, v1.z, v1.w};
        uint32_t w0[4], w1[4];
        #pragma unroll
        for (int i = 0; i < 4; i++) {
            float x0, x1, y0, y1;
            split2(f[2 * i], x0, x1);
            split2(f[2 * i + 1], y0, y1);
            w0[i] = packhf(x0, y0);
            w1[i] = packhf(x1, y1);
        }
        g_a0[t] = make_uint4(w0[0], w0[1], w0[2], w0[3]);
        g_a1[t] = make_uint4(w1[0], w1[1], w1[2], w1[3]);
    } else {                                          // B: (j, n) — n fast
        int q = t - 65536;
        int n = q & 4095, j = q >> 12;
        float f[8];
        #pragma unroll
        for (int i = 0; i < 8; i++)
            f[i] = vvt[(size_t)(j * 8 + i) * 4096 + n];
        uint32_t w0[4], w1[4];
        #pragma unroll
        for (int i = 0; i < 4; i++) {
            float x0, x1, y0, y1;
            split2(f[2 * i], x0, x1);
            split2(f[2 * i + 1], y0, y1);
            w0[i] = packhf(x0, y0);
            w1[i] = packhf(x1, y1);
        }
        g_b0[n * 16 + j] = make_uint4(w0[0], w0[1], w0[2], w0[3]);
        g_b1[n * 16 + j] = make_uint4(w1[0], w1[1], w1[2], w1[3]);
    }
}

// ---------------------------------------------------------------------------
// k1: HMMA fp16 2-term-split GEMM tile (128m x 64n, K=128; x0y0 -> main,
// x0y1s + x1sy0 -> corr, all f32 accum) + fused digitize epilogue.
// 2 CTAs/SM so loads and epilogue of one CTA overlap MMA of the other.
// 256 threads = 8 warps (4m x 2n), warp tile 32m x 32n.
// ---------------------------------------------------------------------------
#define ROWB  272            // bytes per smem row (136 halves)
#define BUFA  (128 * ROWB)   // 34816 B
#define BUFBN (64 * ROWB)    // 17408 B
#define SMEM_DYN (2 * BUFA + 2 * BUFBN)   // 104448 B

__device__ __forceinline__ void run_pass(uint32_t uA, uint32_t uB,
                                         float (*acc)[4][4],
                                         uint32_t a_off, uint32_t b_off) {
    #pragma unroll
    for (int ks = 0; ks < 8; ks++) {
        uint32_t kb = ks * 32;               // 16 halves per k-step
        uint32_t a0[4], a1[4];
        ldm_x4(a0, uA + a_off + kb);
        ldm_x4(a1, uA + a_off + 16 * ROWB + kb);
        #pragma unroll
        for (int nf16 = 0; nf16 < 2; nf16++) {
            uint32_t b[4];
            ldm_x4(b, uB + b_off + nf16 * 16 * ROWB + kb);
            mma16816(acc[0][nf16 * 2],     a0, b[0], b[1]);
            mma16816(acc[0][nf16 * 2 + 1], a0, b[2], b[3]);
            mma16816(acc[1][nf16 * 2],     a1, b[0], b[1]);
            mma16816(acc[1][nf16 * 2 + 1], a1, b[2], b[3]);
        }
    }
}

__global__ void __launch_bounds__(256, 2)
k1_mma(const float* __restrict__ attn,
       const float* __restrict__ diff,
       const float* __restrict__ start) {
    extern __shared__ char dynsm[];
    __shared__ float s_binw[16];
    __shared__ float s_attn[128];
    __shared__ float s_red2[4 * 64];

    const int tid  = threadIdx.x;
    const int lane = tid & 31;
    const int wid  = tid >> 5;
    const int warp_m = wid & 3, warp_n = wid >> 2;
    const int nb = blockIdx.x, mb = blockIdx.y;

    const uint32_t uS  = smem_u32(dynsm);
    const uint32_t uA0 = uS;
    const uint32_t uA1 = uS + BUFA;
    const uint32_t uB0 = uS + 2 * BUFA;
    const uint32_t uB1 = uS + 2 * BUFA + BUFBN;

    if (tid < 128) s_attn[tid] = attn[mb * 128 + tid];
    if (tid == 0) {
        float s0 = start[0], acc = 0.0f;
        for (int i = 0; i < 16; i++) {
            float dv = diff[i];
            acc += (dv > 0.0f) ? dv : 0.0f;
            s_binw[i] = s0 + acc;
        }
    }

    // async loads: group 1 = A0,B0 ; group 2 = A1,B1
    {
        const uint4* ga0 = g_a0 + mb * 2048;
        const uint4* gb0 = g_b0 + nb * 1024;
        #pragma unroll
        for (int c = tid; c < 2048; c += 256) {
            uint32_t d = (uint32_t)(c >> 4) * ROWB + (uint32_t)(c & 15) * 16;
            cp16(uA0 + d, ga0 + c);
        }
        #pragma unroll
        for (int c = tid; c < 1024; c += 256) {
            uint32_t d = (uint32_t)(c >> 4) * ROWB + (uint32_t)(c & 15) * 16;
            cp16(uB0 + d, gb0 + c);
        }
        asm volatile("cp.async.commit_group;" ::: "memory");
        const uint4* ga1 = g_a1 + mb * 2048;
        const uint4* gb1 = g_b1 + nb * 1024;
        #pragma unroll
        for (int c = tid; c < 2048; c += 256) {
            uint32_t d = (uint32_t)(c >> 4) * ROWB + (uint32_t)(c & 15) * 16;
            cp16(uA1 + d, ga1 + c);
        }
        #pragma unroll
        for (int c = tid; c < 1024; c += 256) {
            uint32_t d = (uint32_t)(c >> 4) * ROWB + (uint32_t)(c & 15) * 16;
            cp16(uB1 + d, gb1 + c);
        }
        asm volatile("cp.async.commit_group;" ::: "memory");
    }

    // per-thread ldmatrix lane offsets
    const uint32_t a_off = (uint32_t)(warp_m * 32 + (lane & 15)) * ROWB +
                           (uint32_t)(lane >> 4) * 16;
    const int bn = (lane & 7) + ((lane >> 4) << 3);
    const uint32_t b_off = (uint32_t)(warp_n * 32 + bn) * ROWB +
                           (uint32_t)((lane >> 3) & 1) * 16;

    float accm[2][4][4];     // main: x0*y0
    float accc[2][4][4];     // corr: 2^12*(x0*y1 + x1*y0)
    #pragma unroll
    for (int i = 0; i < 2; i++)
        #pragma unroll
        for (int j = 0; j < 4; j++)
            #pragma unroll
            for (int q = 0; q < 4; q++) { accm[i][j][q] = 0.0f; accc[i][j][q] = 0.0f; }

    asm volatile("cp.async.wait_group 1;" ::: "memory");
    __syncthreads();
    run_pass(uA0, uB0, accm, a_off, b_off);      // x0*y0
    asm volatile("cp.async.wait_group 0;" ::: "memory");
    __syncthreads();
    run_pass(uA0, uB1, accc, a_off, b_off);      // x0*y1s
    run_pass(uA1, uB0, accc, a_off, b_off);      // x1s*y0

    __syncthreads();   // done reading tile buffers; reuse as red[128][68]

    // ---- epilogue: combine, digitize + attn weight -> red, column reduce ----
    float* red = (float*)dynsm;                  // stride 68
    {
        const int r0b = warp_m * 32 + (lane >> 2);
        const int colb = warp_n * 32 + (lane & 3) * 2;
        #pragma unroll
        for (int mf = 0; mf < 2; mf++) {
            int ra = r0b + mf * 16;
            float aa = s_attn[ra], ab = s_attn[ra + 8];
            #pragma unroll
            for (int nf = 0; nf < 4; nf++) {
                int cc = colb + nf * 8;
                float* fm = accm[mf][nf];
                float* fc = accc[mf][nf];
                float s0v = fmaf(fc[0], CORR_SCALE, fm[0]);
                float s1v = fmaf(fc[1], CORR_SCALE, fm[1]);
                float s2v = fmaf(fc[2], CORR_SCALE, fm[2]);
                float s3v = fmaf(fc[3], CORR_SCALE, fm[3]);
                red[ra * 68 + cc]           = aa * binval(s0v, s_binw);
                red[ra * 68 + cc + 1]       = aa * binval(s1v, s_binw);
                red[(ra + 8) * 68 + cc]     = ab * binval(s2v, s_binw);
                red[(ra + 8) * 68 + cc + 1] = ab * binval(s3v, s_binw);
            }
        }
    }
    __syncthreads();
    {
        int col = tid & 63, seg = tid >> 6;      // 4 segs of 32 rows
        float s0 = 0.f, s1 = 0.f;
        #pragma unroll 8
        for (int r = seg * 32; r < seg * 32 + 32; r += 2) {
            s0 += red[r * 68 + col];
            s1 += red[(r + 1) * 68 + col];
        }
        s_red2[seg * 64 + col] = s0 + s1;
    }
    __syncthreads();
    if (tid < 64)
        g_part[mb * NV_ + nb * 64 + tid] =
            (s_red2[tid] + s_red2[64 + tid]) +
            (s_red2[128 + tid] + s_red2[192 + tid]);
}

// ---------------------------------------------------------------------------
// k2: blocked GEMM out[b,j] += sum_{v in split} a[b,v]*phi[j,v].
// grid (4 v-splits, 32 j-tiles of 16); accumulates into out via atomicAdd
// (out zeroed by k0; stream order guarantees k0 -> k1 -> k2).
// ---------------------------------------------------------------------------
__global__ void __launch_bounds__(256)
k2_gemm2(const float* __restrict__ phi, float* __restrict__ out) {
    __shared__ float asum[8 * 1024];
    const int vs = blockIdx.x, jt = blockIdx.y;
    const int tid = threadIdx.x;
    const int vbase = vs * 1024;

    for (int i = tid; i < 8192; i += 256) {
        int b = i >> 10, v = i & 1023;
        int gv = vbase + v;
        asum[i] = (g_part[(4 * b + 0) * NV_ + gv] + g_part[(4 * b + 1) * NV_ + gv]) +
                  (g_part[(4 * b + 2) * NV_ + gv] + g_part[(4 * b + 3) * NV_ + gv]);
    }
    __syncthreads();

    const int wid = tid >> 5, lane = tid & 31;
    const float4* asum4 = (const float4*)asum;
    #pragma unroll 4
    for (int c = 0; c < 16; c++) {
        int cid = wid * 16 + c;
        int jl = cid >> 3, b = cid & 7;
        int j = jt * 16 + jl;
        const float4* p4 = (const float4*)(phi + (size_t)j * NV_ + vbase);
        float acc = 0.f;
        #pragma unroll
        for (int it = 0; it < 8; it++) {
            float4 a4 = asum4[b * 256 + it * 32 + lane];
            float4 pp = p4[it * 32 + lane];
            acc = fmaf(a4.x, pp.x, acc);
            acc = fmaf(a4.y, pp.y, acc);
            acc = fmaf(a4.z, pp.z, acc);
            acc = fmaf(a4.w, pp.w, acc);
        }
        #pragma unroll
        for (int o = 16; o > 0; o >>= 1)
            acc += __shfl_xor_sync(0xffffffffu, acc, o);
        if (lane == 0) atomicAdd(&out[b * NODES_ + j], acc);
    }
}

// ---------------------------------------------------------------------------
extern "C" void kernel_launch(void* const* d_in, const int* in_sizes, int n_in,
                              void* d_out, int out_size) {
    const void*  doc   = d_in[0];
    const float* attn  = (const float*)d_in[1];
    const float* emb   = (const float*)d_in[2];
    const float* vvt   = (const float*)d_in[3];
    const float* phi   = (const float*)d_in[4];
    const float* diff  = (const float*)d_in[5];
    const float* start = (const float*)d_in[6];
    float* out = (float*)d_out;

    static int smem_set = 0;
    if (!smem_set) {
        cudaFuncSetAttribute(k1_mma, cudaFuncAttributeMaxDynamicSharedMemorySize,
                             SMEM_DYN);
        smem_set = 1;
    }

    k0_convert<<<512, 256>>>(doc, emb, vvt, out);
    dim3 g1(NV_ / 64, (B_ * ND_) / 128);           // 64 x 32
    k1_mma<<<g1, 256, SMEM_DYN>>>(attn, diff, start);
    dim3 g2(4, 32);
    k2_gemm2<<<g2, 256>>>(phi, out);
}